// round 1
// baseline (speedup 1.0000x reference)
#include <cuda_runtime.h>

// Problem: out[b,s,e] = sum_i inp[b,i,s] * emb[i,e]
//   inp: [64][64][4096] f32   emb: [64][64] f32   out: [64][4096][64] f32
// GEMM view: M=E=64, K=I=64, N=B*S=262144.
//
// Strategy: one thread per s-column. 64 accumulators kept as 32 packed f32x2
// (fma.rn.f32x2 — ptxas never auto-fuses, so inline PTX). emb staged in smem,
// read at warp-uniform addresses (broadcast, conflict-free). Input loads are
// fully coalesced (warp = 32 consecutive s). Output: 16 STG.128 per thread.

#define BATCH 64
#define ISZ   64
#define ESZ   64
#define SEQ   4096
#define TPB   128   // threads per block; block covers 128 s of one batch

__global__ __launch_bounds__(TPB) void embed_f32x2_kernel(
    const float* __restrict__ inp,
    const float* __restrict__ emb,
    float* __restrict__ out)
{
    // emb as [i][e/2] packed 64-bit words; 16 KB
    __shared__ __align__(16) unsigned long long semb[ISZ * ESZ / 2];

    const int tid = threadIdx.x;

    // Cooperative load of emb: 4096 floats = 1024 float4, 8 per thread.
    {
        const float4* g4 = reinterpret_cast<const float4*>(emb);
        float4* s4 = reinterpret_cast<float4*>(semb);
        #pragma unroll
        for (int k = 0; k < 8; k++)
            s4[tid + k * TPB] = g4[tid + k * TPB];
    }
    __syncthreads();

    const int b = blockIdx.y;
    const int s = blockIdx.x * TPB + tid;

    const float* ip = inp + ((long)b * ISZ) * SEQ + s;

    unsigned long long acc[ESZ / 2];
    #pragma unroll
    for (int j = 0; j < ESZ / 2; j++) acc[j] = 0ull;

    #pragma unroll 2
    for (int i = 0; i < ISZ; i++) {
        float x = __ldg(ip + (long)i * SEQ);
        unsigned long long x2;
        asm("mov.b64 %0, {%1, %1};" : "=l"(x2) : "f"(x));
        const unsigned long long* wrow = &semb[i * (ESZ / 2)];
        #pragma unroll
        for (int j = 0; j < ESZ / 2; j++) {
            unsigned long long w = wrow[j];
            asm("fma.rn.f32x2 %0, %1, %2, %0;"
                : "+l"(acc[j]) : "l"(x2), "l"(w));
        }
    }

    // Write 64 contiguous floats for this (b, s).
    float4* o4 = reinterpret_cast<float4*>(out + (((long)b * SEQ + s) * ESZ));
    #pragma unroll
    for (int j = 0; j < ESZ / 4; j++) {
        union { unsigned long long u; float2 f; } lo, hi;
        lo.u = acc[2 * j];
        hi.u = acc[2 * j + 1];
        o4[j] = make_float4(lo.f.x, lo.f.y, hi.f.x, hi.f.y);
    }
}

extern "C" void kernel_launch(void* const* d_in, const int* in_sizes, int n_in,
                              void* d_out, int out_size)
{
    const float* inp = (const float*)d_in[0];   // [64][64][4096]
    const float* emb = (const float*)d_in[1];   // [64][64]
    float* out = (float*)d_out;                 // [64][4096][64]

    dim3 grid(SEQ / TPB, BATCH);
    embed_f32x2_kernel<<<grid, TPB>>>(inp, emb, out);
}

// round 4
// speedup vs baseline: 1.5519x; 1.5519x over previous
#include <cuda_runtime.h>
#include <cuda_bf16.h>
#include <cstdint>

// out[b,s,e] = sum_i inp[b,i,s] * emb[i,e]
//   inp: [64][64][4096] f32, emb: [64][64] f32, out: [64][4096][64] f32
// Per CTA tile: D[64 s][64 e] = A[64 s][64 i] * B[64 i][64 e]
// Split-precision bf16 on mma.sync m16n8k16 (sm_100 baseline PTX):
//   x = xh + xl, w = wh + wl;  D = xh*wh + xl*wh + xh*wl  (residual ~1e-5)

#define BATCH  64
#define ISZ    64
#define ESZ    64
#define SEQ    4096
#define TILE_S 64
#define TPB    256

__device__ __forceinline__ uint32_t sw128(uint32_t off) {
    return off ^ ((off >> 3) & 0x70);
}

__device__ __forceinline__ uint32_t pack_bf2(__nv_bfloat16 lo, __nv_bfloat16 hi) {
    return (uint32_t)__bfloat16_as_ushort(lo) |
           ((uint32_t)__bfloat16_as_ushort(hi) << 16);
}

__device__ __forceinline__ void split_bf16(float x, __nv_bfloat16& h, __nv_bfloat16& l) {
    h = __float2bfloat16(x);
    l = __float2bfloat16(x - __bfloat162float(h));
}

__device__ __forceinline__ void mma_bf16(float* c, const uint32_t* a, const uint32_t* b) {
    asm volatile(
        "mma.sync.aligned.m16n8k16.row.col.f32.bf16.bf16.f32 "
        "{%0,%1,%2,%3}, {%4,%5,%6,%7}, {%8,%9}, {%0,%1,%2,%3};"
        : "+f"(c[0]), "+f"(c[1]), "+f"(c[2]), "+f"(c[3])
        : "r"(a[0]), "r"(a[1]), "r"(a[2]), "r"(a[3]),
          "r"(b[0]), "r"(b[1]));
}

__device__ __forceinline__ void ldmatrix_x4(uint32_t* r, uint32_t addr) {
    asm volatile(
        "ldmatrix.sync.aligned.m8n8.x4.shared.b16 {%0,%1,%2,%3}, [%4];"
        : "=r"(r[0]), "=r"(r[1]), "=r"(r[2]), "=r"(r[3])
        : "r"(addr));
}

__global__ __launch_bounds__(TPB) void embed_mma_kernel(
    const float* __restrict__ inp,
    const float* __restrict__ emb,
    float* __restrict__ out)
{
    // A tiles in smem: 64 rows (s) x 128 bytes (64 bf16 i), SW128 swizzled.
    __shared__ __align__(1024) char smA_hi[TILE_S * 128];
    __shared__ __align__(1024) char smA_lo[TILE_S * 128];

    const int tid  = threadIdx.x;
    const int wid  = tid >> 5;
    const int lane = tid & 31;

    const int b      = blockIdx.y;
    const int s_base = blockIdx.x * TILE_S;

    // Warp tile: 16 s x 32 e
    const int s_sub  = (wid & 3) * 16;
    const int e_half = (wid >> 2) * 32;

    // ---- Build B fragments in registers (emb is L2-resident, 16 KB) ----
    // B frag (col) m16n8k16: reg0 = B[k0][n],B[k0+1][n]; reg1 = B[k0+8..9][n]
    // n = lane/4, k0 = (lane%4)*2 (+16 per k-step)
    uint32_t bh[4][4][2], bl[4][4][2];
    {
        const int n_l = lane >> 2;
        const int c   = (lane & 3) * 2;
        #pragma unroll
        for (int nt = 0; nt < 4; nt++) {
            const int e = e_half + nt * 8 + n_l;
            #pragma unroll
            for (int kk = 0; kk < 4; kk++) {
                const int k0 = kk * 16 + c;
                float w00 = emb[(k0    ) * ESZ + e];
                float w01 = emb[(k0 + 1) * ESZ + e];
                float w10 = emb[(k0 + 8) * ESZ + e];
                float w11 = emb[(k0 + 9) * ESZ + e];
                __nv_bfloat16 h, l, h2, l2;
                split_bf16(w00, h, l); split_bf16(w01, h2, l2);
                bh[nt][kk][0] = pack_bf2(h, h2);
                bl[nt][kk][0] = pack_bf2(l, l2);
                split_bf16(w10, h, l); split_bf16(w11, h2, l2);
                bh[nt][kk][1] = pack_bf2(h, h2);
                bl[nt][kk][1] = pack_bf2(l, l2);
            }
        }
    }

    // ---- Stage A: gmem [i][s] -> smem [s][i] bf16 hi/lo, SW128 ----
    // thread: s_local = tid%64, i range = (tid/64)*16 .. +15, pairs of i.
    {
        const int s_l  = tid & 63;
        const int ig   = tid >> 6;            // 0..3 -> 16 i each
        const float* ip = inp + ((long)b * ISZ + ig * 16) * SEQ + s_base + s_l;
        #pragma unroll
        for (int p = 0; p < 8; p++) {         // pairs of i
            float x0 = ip[(long)(2 * p    ) * SEQ];
            float x1 = ip[(long)(2 * p + 1) * SEQ];
            __nv_bfloat16 h0, l0, h1, l1;
            split_bf16(x0, h0, l0);
            split_bf16(x1, h1, l1);
            uint32_t off = sw128((uint32_t)(s_l * 128 + (ig * 16 + 2 * p) * 2));
            *(uint32_t*)(smA_hi + off) = pack_bf2(h0, h1);
            *(uint32_t*)(smA_lo + off) = pack_bf2(l0, l1);
        }
    }
    __syncthreads();

    // ---- ldmatrix addresses for this warp's 16x16 A tiles ----
    // x4 order: m0 = rows 0-7 k-lo, m1 = rows 8-15 k-lo, m2 = rows 0-7 k-hi, m3 = rows 8-15 k-hi
    const int a_row  = s_sub + ((lane >> 3) & 1) * 8 + (lane & 7);
    const int a_colb = (lane >> 4) * 16;     // 0 or 16 bytes (k-hi half)
    const uint32_t base_hi = (uint32_t)__cvta_generic_to_shared(smA_hi);
    const uint32_t base_lo = (uint32_t)__cvta_generic_to_shared(smA_lo);

    float acc[4][4];
    #pragma unroll
    for (int nt = 0; nt < 4; nt++)
        #pragma unroll
        for (int r = 0; r < 4; r++) acc[nt][r] = 0.0f;

    #pragma unroll
    for (int kk = 0; kk < 4; kk++) {
        const uint32_t off = sw128((uint32_t)(a_row * 128 + kk * 32 + a_colb));
        uint32_t ahi[4], alo[4];
        ldmatrix_x4(ahi, base_hi + off);
        ldmatrix_x4(alo, base_lo + off);
        #pragma unroll
        for (int nt = 0; nt < 4; nt++) mma_bf16(acc[nt], ahi, bh[nt][kk]);
        #pragma unroll
        for (int nt = 0; nt < 4; nt++) mma_bf16(acc[nt], alo, bh[nt][kk]);
        #pragma unroll
        for (int nt = 0; nt < 4; nt++) mma_bf16(acc[nt], ahi, bl[nt][kk]);
    }

    // ---- Epilogue: C frag -> out[b][s][e] ----
    // c0,c1 at (m = lane/4, n = (lane%4)*2), c2,c3 at m+8.
    {
        const int m = lane >> 2;
        const int n = (lane & 3) * 2;
        const long s0 = (long)b * SEQ + s_base + s_sub + m;
        #pragma unroll
        for (int nt = 0; nt < 4; nt++) {
            const int e = e_half + nt * 8 + n;
            *(float2*)(out + s0 * ESZ + e) =
                make_float2(acc[nt][0], acc[nt][1]);
            *(float2*)(out + (s0 + 8) * ESZ + e) =
                make_float2(acc[nt][2], acc[nt][3]);
        }
    }
}

extern "C" void kernel_launch(void* const* d_in, const int* in_sizes, int n_in,
                              void* d_out, int out_size)
{
    const float* inp = (const float*)d_in[0];   // [64][64][4096]
    const float* emb = (const float*)d_in[1];   // [64][64]
    float* out = (float*)d_out;                 // [64][4096][64]

    dim3 grid(SEQ / TILE_S, BATCH);
    embed_mma_kernel<<<grid, TPB>>>(inp, emb, out);
}